// round 5
// baseline (speedup 1.0000x reference)
#include <cuda_runtime.h>
#include <cuda_bf16.h>
#include <cstdint>

// Problem constants
#define TOT_ROWS 16384   // B*N = 4*4096
#define DIM      1024
#define BOT      64
#define MTILE    64      // rows per CTA
#define NTHR     512
#define NCH      128     // N-chunk for GEMM2
#define NNC      8       // DIM/NCH

#define WDSTRIDE 136     // wd row stride in bf16 (128 data + 8 pad) -> 272B, conflict-free
#define SPAD     72      // gs/wu row stride in bf16 -> 144B, conflict-free

// dynamic smem layout (bytes)
#define SMEM_WD_BYTES (2 * 64 * WDSTRIDE * 2)          // 69632 (union: wu[2][128][72] = 36864)
#define SMEM_GS_OFF   SMEM_WD_BYTES
#define SMEM_GS_BYTES (64 * SPAD * 2)                  // 9216
#define SMEM_CF_OFF   (SMEM_GS_OFF + SMEM_GS_BYTES)
#define SMEM_TOTAL    (SMEM_CF_OFF + 512)              // 79360

// ---------------- device scratch ----------------
__device__ __nv_bfloat16 g_WdT[BOT * DIM];   // [j][d] = bf16(norm_w[d] * w_down[d][j])
__device__ __nv_bfloat16 g_WuT[DIM * BOT];   // [n][k] = bf16(w_up[k][n])
__device__ float         g_cf[2 * BOT];      // c[64], f[64]

// ---------------- helpers ----------------
__device__ __forceinline__ void cp16(void* s, const void* g) {
    uint32_t sa = (uint32_t)__cvta_generic_to_shared(s);
    asm volatile("cp.async.cg.shared.global [%0], [%1], 16;\n" :: "r"(sa), "l"(g));
}
__device__ __forceinline__ void cp_commit() { asm volatile("cp.async.commit_group;\n"); }
__device__ __forceinline__ void cp_wait0()  { asm volatile("cp.async.wait_group 0;\n"); }

__device__ __forceinline__ void mma_bf16(float* d, const uint32_t* a, const uint32_t* b) {
    asm volatile(
        "mma.sync.aligned.m16n8k16.row.col.f32.bf16.bf16.f32 "
        "{%0,%1,%2,%3}, {%4,%5,%6,%7}, {%8,%9}, {%0,%1,%2,%3};\n"
        : "+f"(d[0]), "+f"(d[1]), "+f"(d[2]), "+f"(d[3])
        : "r"(a[0]), "r"(a[1]), "r"(a[2]), "r"(a[3]), "r"(b[0]), "r"(b[1]));
}
__device__ __forceinline__ void ldsm_x4(uint32_t& r0, uint32_t& r1, uint32_t& r2, uint32_t& r3,
                                        const void* p) {
    uint32_t a = (uint32_t)__cvta_generic_to_shared(p);
    asm volatile("ldmatrix.sync.aligned.m8n8.x4.shared.b16 {%0,%1,%2,%3}, [%4];\n"
                 : "=r"(r0), "=r"(r1), "=r"(r2), "=r"(r3) : "r"(a));
}
__device__ __forceinline__ uint32_t pack_bf2(float a, float b) {
    __nv_bfloat162 h2 = __floats2bfloat162_rn(a, b);
    return *reinterpret_cast<uint32_t*>(&h2);
}

// ---------------- prep: weight transpose/convert + c/f ----------------
// grid 17: blocks 0-7 -> WdT, 8-15 -> WuT, 16 -> c/f
__global__ void prep_kernel(const float* __restrict__ norm_w,
                            const float* __restrict__ norm_b,
                            const float* __restrict__ w_down,
                            const float* __restrict__ b_down,
                            const float* __restrict__ w_up)
{
    __shared__ float s[8704];
    const int b = blockIdx.x, tid = threadIdx.x;

    if (b < 8) {
        const int d0 = b * 128;
        float (*sd)[65] = reinterpret_cast<float(*)[65]>(s);   // 128 x 65
        for (int i = tid; i < 128 * 64 / 4; i += 256) {
            int idx = i * 4; int d = idx >> 6; int j = idx & 63;
            float4 v = *(const float4*)(w_down + (size_t)(d0 + d) * 64 + j);
            sd[d][j] = v.x; sd[d][j + 1] = v.y; sd[d][j + 2] = v.z; sd[d][j + 3] = v.w;
        }
        __syncthreads();
        for (int q = tid; q < 64 * 16; q += 256) {
            int j = q >> 4; int d8 = q & 15;
            __nv_bfloat16 tmp[8];
#pragma unroll
            for (int e = 0; e < 8; e++) {
                int d = d8 * 8 + e;
                tmp[e] = __float2bfloat16(norm_w[d0 + d] * sd[d][j]);
            }
            *(uint4*)(g_WdT + (size_t)j * DIM + d0 + d8 * 8) = *(uint4*)tmp;
        }
    } else if (b < 16) {
        const int n0 = (b - 8) * 128;
        float (*su)[130] = reinterpret_cast<float(*)[130]>(s); // 64 x 130
        for (int i = tid; i < 64 * 128 / 4; i += 256) {
            int idx = i * 4; int k = idx >> 7; int n = idx & 127;
            float4 v = *(const float4*)(w_up + (size_t)k * DIM + n0 + n);
            su[k][n] = v.x; su[k][n + 1] = v.y; su[k][n + 2] = v.z; su[k][n + 3] = v.w;
        }
        __syncthreads();
        for (int q = tid; q < 128 * 8; q += 256) {
            int n = q >> 3; int k8 = q & 7;
            __nv_bfloat16 tmp[8];
#pragma unroll
            for (int e = 0; e < 8; e++)
                tmp[e] = __float2bfloat16(su[k8 * 8 + e][n]);
            *(uint4*)(g_WuT + (size_t)(n0 + n) * BOT + k8 * 8) = *(uint4*)tmp;
        }
    } else {
        // c_j = sum_d norm_w[d]*w_down[d][j]; f_j = b_down[j] + sum_d norm_b[d]*w_down[d][j]
        float* sc = s; float* sf = s + 256;
        const int j = tid & 63, part = tid >> 6;     // 4 d-quarters
        float c = 0.f, f = 0.f;
        for (int d = part * 256; d < part * 256 + 256; d++) {
            float w = w_down[(size_t)d * 64 + j];
            c += norm_w[d] * w;
            f += norm_b[d] * w;
        }
        sc[tid] = c; sf[tid] = f;
        __syncthreads();
        if (tid < 64) {
            c = sc[tid] + sc[tid + 64] + sc[tid + 128] + sc[tid + 192];
            f = sf[tid] + sf[tid + 64] + sf[tid + 128] + sf[tid + 192];
            g_cf[tid] = c;
            g_cf[64 + tid] = f + b_down[tid];
        }
    }
}

// ---------------- main fused kernel ----------------
__global__ __launch_bounds__(NTHR, 2)
void adapter_kernel(const float* __restrict__ x,
                    const float* __restrict__ b_up,
                    const float* __restrict__ scale_p,
                    float* __restrict__ out)
{
    extern __shared__ __align__(16) char smem_raw[];
    __nv_bfloat16* wd = (__nv_bfloat16*)smem_raw;                 // [2][64][WDSTRIDE]
    __nv_bfloat16* wu = (__nv_bfloat16*)smem_raw;                 // [2][128][SPAD]
    __nv_bfloat16* gs = (__nv_bfloat16*)(smem_raw + SMEM_GS_OFF); // [64][SPAD]
    float*         cf = (float*)(smem_raw + SMEM_CF_OFF);         // [128]

    const int tid  = threadIdx.x;
    const int warp = tid >> 5, lane = tid & 31;
    const int g    = lane >> 2, t4 = lane & 3;     // mma quad decomposition
    const int wm   = warp >> 2, wn = warp & 3;     // 4x4 warp grid
    const int row0 = blockIdx.x * MTILE;

    if (tid < 128) cf[tid] = g_cf[tid];

    // wd cp.async mapping: 64 rows x (8 thr/row x 16 bf16)
    const int wdj = tid >> 3, wdc = (tid & 7) * 16;
    // wu cp.async mapping: 128 rows x (4 thr/row x 16 bf16)
    const int wun = tid >> 2, wuc = (tid & 3) * 16;

    // ldmatrix lane address components
    const int blsA_row  = wn * 16 + ((lane >> 4) << 3) + (lane & 7);   // phase-A B (wd)
    const int bls_koff  = ((lane >> 3) & 1) << 3;
    const int alsB_row  = wm * 16 + (lane & 15);                       // phase-B A (gs)
    const int alsB_koff = (lane >> 4) << 3;
    const int blsB_row0 = wn * 32 + ((lane >> 4) << 3) + (lane & 7);   // phase-B B (wu) sub-pair 0
    const int blsB_row1 = blsB_row0 + 16;                              // sub-pair 1

    // ---- phase A prologue: wd span0 + x chunk 0,1 ----
    cp16(wd + (size_t)wdj * WDSTRIDE + wdc,     g_WdT + (size_t)wdj * DIM + wdc);
    cp16(wd + (size_t)wdj * WDSTRIDE + wdc + 8, g_WdT + (size_t)wdj * DIM + wdc + 8);
    cp_commit();

    const float* xr = x + (size_t)(row0 + wm * 16 + g) * DIM + t4 * 2;
    float2 pf[2][4];
#pragma unroll
    for (int p = 0; p < 2; p++) {
        const float* q = xr + p * 16;
        pf[p][0] = *(const float2*)(q);
        pf[p][1] = *(const float2*)(q + 8);
        pf[p][2] = *(const float2*)(q + 8 * DIM);
        pf[p][3] = *(const float2*)(q + 8 * DIM + 8);
    }

    float s1a = 0.f, s2a = 0.f, s1b = 0.f, s2b = 0.f;
    float acc1[2][4] = {};

    // ---- phase A: direct-from-global A frags + stats; wd double-buffered in 128-k spans ----
#pragma unroll 2
    for (int c = 0; c < 64; c++) {
        if ((c & 7) == 0) {
            cp_wait0();
            __syncthreads();                  // wd buffer (c>>3)&1 ready; other buffer free
            int span = c >> 3;
            if (span + 1 < 8) {
                __nv_bfloat16* dst = wd + (size_t)(((span + 1) & 1) * 64 + wdj) * WDSTRIDE + wdc;
                const __nv_bfloat16* src = g_WdT + (size_t)wdj * DIM + (span + 1) * 128 + wdc;
                cp16(dst, src);
                cp16(dst + 8, src + 8);
                cp_commit();
            }
        }
        float2* v = pf[c & 1];
        // stats (row g from v0,v1; row g+8 from v2,v3)
        s1a += v[0].x + v[0].y + v[1].x + v[1].y;
        s2a += v[0].x * v[0].x + v[0].y * v[0].y + v[1].x * v[1].x + v[1].y * v[1].y;
        s1b += v[2].x + v[2].y + v[3].x + v[3].y;
        s2b += v[2].x * v[2].x + v[2].y * v[2].y + v[3].x * v[3].x + v[3].y * v[3].y;
        // A fragment (row g lo, row g+8 lo, row g hi, row g+8 hi)
        uint32_t afr[4];
        afr[0] = pack_bf2(v[0].x, v[0].y);
        afr[1] = pack_bf2(v[2].x, v[2].y);
        afr[2] = pack_bf2(v[1].x, v[1].y);
        afr[3] = pack_bf2(v[3].x, v[3].y);
        if (c + 2 < 64) {                     // 2-deep register prefetch of x
            const float* q = xr + (c + 2) * 16;
            v[0] = *(const float2*)(q);
            v[1] = *(const float2*)(q + 8);
            v[2] = *(const float2*)(q + 8 * DIM);
            v[3] = *(const float2*)(q + 8 * DIM + 8);
        }
        // B fragments for both 8-col groups via one ldmatrix.x4
        uint32_t b0, b1, b2, b3;
        ldsm_x4(b0, b1, b2, b3,
                wd + (size_t)((((c >> 3) & 1) * 64) + blsA_row) * WDSTRIDE + (c & 7) * 16 + bls_koff);
        uint32_t bf0[2] = {b0, b1}, bf1[2] = {b2, b3};
        mma_bf16(acc1[0], afr, bf0);
        mma_bf16(acc1[1], afr, bf1);
    }

    // ---- LN stats (quad reduce; all 4 lanes of quad end with full row sums) ----
#pragma unroll
    for (int off = 1; off <= 2; off <<= 1) {
        s1a += __shfl_xor_sync(0xffffffffu, s1a, off);
        s2a += __shfl_xor_sync(0xffffffffu, s2a, off);
        s1b += __shfl_xor_sync(0xffffffffu, s1b, off);
        s2b += __shfl_xor_sync(0xffffffffu, s2b, off);
    }
    const float mua = s1a * (1.0f / 1024.0f);
    const float rsa = rsqrtf(s2a * (1.0f / 1024.0f) - mua * mua + 1e-5f);
    const float mub = s1b * (1.0f / 1024.0f);
    const float rsb = rsqrtf(s2b * (1.0f / 1024.0f) - mub * mub + 1e-5f);

    __syncthreads();   // all wd reads done -> union region free for wu

    // prefetch wu chunk 0
    cp16(wu + (size_t)wun * SPAD + wuc,     g_WuT + (size_t)wun * BOT + wuc);
    cp16(wu + (size_t)wun * SPAD + wuc + 8, g_WuT + (size_t)wun * BOT + wuc + 8);
    cp_commit();

    // ---- affine correction + exact GELU -> gs ----
#pragma unroll
    for (int h = 0; h < 2; h++) {
        int j0 = wn * 16 + h * 8 + t4 * 2;
        float c0 = cf[j0], c1 = cf[j0 + 1];
        float f0 = cf[64 + j0], f1 = cf[64 + j0 + 1];
        float z00 = rsa * (acc1[h][0] - mua * c0) + f0;
        float z01 = rsa * (acc1[h][1] - mua * c1) + f1;
        float z10 = rsb * (acc1[h][2] - mub * c0) + f0;
        float z11 = rsb * (acc1[h][3] - mub * c1) + f1;
        z00 = 0.5f * z00 * (1.0f + erff(z00 * 0.70710678118f));
        z01 = 0.5f * z01 * (1.0f + erff(z01 * 0.70710678118f));
        z10 = 0.5f * z10 * (1.0f + erff(z10 * 0.70710678118f));
        z11 = 0.5f * z11 * (1.0f + erff(z11 * 0.70710678118f));
        *(uint32_t*)&gs[(wm * 16 + g) * SPAD + j0]     = pack_bf2(z00, z01);
        *(uint32_t*)&gs[(wm * 16 + g + 8) * SPAD + j0] = pack_bf2(z10, z11);
    }
    const float scale = *scale_p;

    // ---- phase B: GEMM2 (gelu @ w_up), N-chunked, fused residual epilogue ----
#pragma unroll 1
    for (int nc = 0; nc < NNC; nc++) {
        const int cur = nc & 1;
        cp_wait0();
        __syncthreads();   // wu[cur] + gs visible; wu[1-cur] readers done
        if (nc + 1 < NNC) {
            __nv_bfloat16* dst = wu + (size_t)((1 - cur) * 128 + wun) * SPAD + wuc;
            const __nv_bfloat16* src = g_WuT + (size_t)((nc + 1) * NCH + wun) * BOT + wuc;
            cp16(dst, src);
            cp16(dst + 8, src + 8);
            cp_commit();
        }
        float acc2[4][4] = {};
#pragma unroll
        for (int ks = 0; ks < 4; ks++) {
            uint32_t afr[4];
            ldsm_x4(afr[0], afr[1], afr[2], afr[3],
                    gs + (size_t)alsB_row * SPAD + ks * 16 + alsB_koff);
            uint32_t b0, b1, b2, b3;
            ldsm_x4(b0, b1, b2, b3,
                    wu + (size_t)(cur * 128 + blsB_row0) * SPAD + ks * 16 + bls_koff);
            uint32_t p0[2] = {b0, b1}, p1[2] = {b2, b3};
            mma_bf16(acc2[0], afr, p0);
            mma_bf16(acc2[1], afr, p1);
            ldsm_x4(b0, b1, b2, b3,
                    wu + (size_t)(cur * 128 + blsB_row1) * SPAD + ks * 16 + bls_koff);
            uint32_t p2[2] = {b0, b1}, p3[2] = {b2, b3};
            mma_bf16(acc2[2], afr, p2);
            mma_bf16(acc2[3], afr, p3);
        }
        // epilogue: out = x + scale*(h + b_up)
        const int rowa = row0 + wm * 16 + g;
#pragma unroll
        for (int sub = 0; sub < 4; sub++) {
            int col = nc * NCH + wn * 32 + sub * 8 + t4 * 2;
            float2 bu = *(const float2*)(b_up + col);
            float2 xa = *(const float2*)(x + (size_t)rowa * DIM + col);
            float2 xb = *(const float2*)(x + (size_t)(rowa + 8) * DIM + col);
            float2 oa, ob;
            oa.x = xa.x + scale * (acc2[sub][0] + bu.x);
            oa.y = xa.y + scale * (acc2[sub][1] + bu.y);
            ob.x = xb.x + scale * (acc2[sub][2] + bu.x);
            ob.y = xb.y + scale * (acc2[sub][3] + bu.y);
            *(float2*)(out + (size_t)rowa * DIM + col)       = oa;
            *(float2*)(out + (size_t)(rowa + 8) * DIM + col) = ob;
        }
    }
}

// ---------------- launch ----------------
extern "C" void kernel_launch(void* const* d_in, const int* in_sizes, int n_in,
                              void* d_out, int out_size)
{
    const float* x      = (const float*)d_in[0];
    const float* norm_w = (const float*)d_in[1];
    const float* norm_b = (const float*)d_in[2];
    const float* w_down = (const float*)d_in[3];
    const float* b_down = (const float*)d_in[4];
    const float* w_up   = (const float*)d_in[5];
    const float* b_up   = (const float*)d_in[6];
    const float* scale  = (const float*)d_in[7];
    float* out = (float*)d_out;

    cudaFuncSetAttribute(adapter_kernel,
                         cudaFuncAttributeMaxDynamicSharedMemorySize, SMEM_TOTAL);

    prep_kernel<<<17, 256>>>(norm_w, norm_b, w_down, b_down, w_up);
    adapter_kernel<<<TOT_ROWS / MTILE, NTHR, SMEM_TOTAL>>>(x, b_up, scale, out);
}

// round 7
// speedup vs baseline: 1.2624x; 1.2624x over previous
#include <cuda_runtime.h>
#include <cuda_bf16.h>
#include <cstdint>

// Problem constants
#define TOT_ROWS 16384   // B*N = 4*4096
#define DIM      1024
#define BOT      64
#define MTILE    64      // rows per CTA
#define NTHR     512
#define KC       128     // K-chunk for GEMM1
#define NKC      8       // DIM/KC
#define NCH      128     // N-chunk for GEMM2
#define NNC      8       // DIM/NCH

#define WSTR     136     // xs/wd row stride in bf16: 272B -> 4-bank row step, conflict-free
#define SPAD     72      // gs/wu row stride in bf16: 144B, conflict-free

// dynamic smem layout (bytes)
#define SMEM_XS_OFF  0                         // xs[2][64][136] bf16 = 34816
#define SMEM_WD_OFF  34816                     // wd[2][64][136] bf16 = 34816 (ends 69632)
#define SMEM_WU_OFF  0                         // phase-B union: wu[2][128][72] = 36864
#define SMEM_GS_OFF  69632                     // gs[64][72] = 9216
#define SMEM_CF_OFF  78848                     // 128 floats
#define SMEM_MU_OFF  79360                     // 64 floats
#define SMEM_RS_OFF  79616                     // 64 floats
#define SMEM_TOTAL   79872

// ---------------- device scratch ----------------
__device__ __nv_bfloat16 g_WdT[BOT * DIM];   // [j][d] = bf16(norm_w[d] * w_down[d][j])
__device__ __nv_bfloat16 g_WuT[DIM * BOT];   // [n][k] = bf16(w_up[k][n])
__device__ float         g_cf[2 * BOT];      // c[64], f[64]

// ---------------- helpers ----------------
__device__ __forceinline__ void cp16(void* s, const void* g) {
    uint32_t sa = (uint32_t)__cvta_generic_to_shared(s);
    asm volatile("cp.async.cg.shared.global [%0], [%1], 16;\n" :: "r"(sa), "l"(g));
}
__device__ __forceinline__ void cp_commit() { asm volatile("cp.async.commit_group;\n"); }
__device__ __forceinline__ void cp_wait0()  { asm volatile("cp.async.wait_group 0;\n"); }

__device__ __forceinline__ void mma_bf16(float* d, const uint32_t* a, const uint32_t* b) {
    asm volatile(
        "mma.sync.aligned.m16n8k16.row.col.f32.bf16.bf16.f32 "
        "{%0,%1,%2,%3}, {%4,%5,%6,%7}, {%8,%9}, {%0,%1,%2,%3};\n"
        : "+f"(d[0]), "+f"(d[1]), "+f"(d[2]), "+f"(d[3])
        : "r"(a[0]), "r"(a[1]), "r"(a[2]), "r"(a[3]), "r"(b[0]), "r"(b[1]));
}
__device__ __forceinline__ void ldsm_x4(uint32_t& r0, uint32_t& r1, uint32_t& r2, uint32_t& r3,
                                        const void* p) {
    uint32_t a = (uint32_t)__cvta_generic_to_shared(p);
    asm volatile("ldmatrix.sync.aligned.m8n8.x4.shared.b16 {%0,%1,%2,%3}, [%4];\n"
                 : "=r"(r0), "=r"(r1), "=r"(r2), "=r"(r3) : "r"(a));
}
__device__ __forceinline__ uint32_t pack_bf2(float a, float b) {
    __nv_bfloat162 h2 = __floats2bfloat162_rn(a, b);
    return *reinterpret_cast<uint32_t*>(&h2);
}

// ---------------- prep: weight transpose/convert + c/f ----------------
// grid 17: blocks 0-7 -> WdT, 8-15 -> WuT, 16 -> c/f
__global__ void prep_kernel(const float* __restrict__ norm_w,
                            const float* __restrict__ norm_b,
                            const float* __restrict__ w_down,
                            const float* __restrict__ b_down,
                            const float* __restrict__ w_up)
{
    __shared__ float s[8704];
    const int b = blockIdx.x, tid = threadIdx.x;

    if (b < 8) {
        const int d0 = b * 128;
        float (*sd)[65] = reinterpret_cast<float(*)[65]>(s);   // 128 x 65
        for (int i = tid; i < 128 * 64 / 4; i += 256) {
            int idx = i * 4; int d = idx >> 6; int j = idx & 63;
            float4 v = *(const float4*)(w_down + (size_t)(d0 + d) * 64 + j);
            sd[d][j] = v.x; sd[d][j + 1] = v.y; sd[d][j + 2] = v.z; sd[d][j + 3] = v.w;
        }
        __syncthreads();
        for (int q = tid; q < 64 * 16; q += 256) {
            int j = q >> 4; int d8 = q & 15;
            __nv_bfloat16 tmp[8];
#pragma unroll
            for (int e = 0; e < 8; e++) {
                int d = d8 * 8 + e;
                tmp[e] = __float2bfloat16(norm_w[d0 + d] * sd[d][j]);
            }
            *(uint4*)(g_WdT + (size_t)j * DIM + d0 + d8 * 8) = *(uint4*)tmp;
        }
    } else if (b < 16) {
        const int n0 = (b - 8) * 128;
        float (*su)[130] = reinterpret_cast<float(*)[130]>(s); // 64 x 130
        for (int i = tid; i < 64 * 128 / 4; i += 256) {
            int idx = i * 4; int k = idx >> 7; int n = idx & 127;
            float4 v = *(const float4*)(w_up + (size_t)k * DIM + n0 + n);
            su[k][n] = v.x; su[k][n + 1] = v.y; su[k][n + 2] = v.z; su[k][n + 3] = v.w;
        }
        __syncthreads();
        for (int q = tid; q < 128 * 8; q += 256) {
            int n = q >> 3; int k8 = q & 7;
            __nv_bfloat16 tmp[8];
#pragma unroll
            for (int e = 0; e < 8; e++)
                tmp[e] = __float2bfloat16(su[k8 * 8 + e][n]);
            *(uint4*)(g_WuT + (size_t)(n0 + n) * BOT + k8 * 8) = *(uint4*)tmp;
        }
    } else {
        float* sc = s; float* sf = s + 256;
        const int j = tid & 63, part = tid >> 6;     // 4 d-quarters
        float c = 0.f, f = 0.f;
        for (int d = part * 256; d < part * 256 + 256; d++) {
            float w = w_down[(size_t)d * 64 + j];
            c += norm_w[d] * w;
            f += norm_b[d] * w;
        }
        sc[tid] = c; sf[tid] = f;
        __syncthreads();
        if (tid < 64) {
            c = sc[tid] + sc[tid + 64] + sc[tid + 128] + sc[tid + 192];
            f = sf[tid] + sf[tid + 64] + sf[tid + 128] + sf[tid + 192];
            g_cf[tid] = c;
            g_cf[64 + tid] = f + b_down[tid];
        }
    }
}

// ---------------- main fused kernel ----------------
__global__ __launch_bounds__(NTHR, 2)
void adapter_kernel(const float* __restrict__ x,
                    const float* __restrict__ b_up,
                    const float* __restrict__ scale_p,
                    float* __restrict__ out)
{
    extern __shared__ __align__(16) char smem_raw[];
    __nv_bfloat16* xs = (__nv_bfloat16*)(smem_raw + SMEM_XS_OFF);  // [2][64][WSTR]
    __nv_bfloat16* wd = (__nv_bfloat16*)(smem_raw + SMEM_WD_OFF);  // [2][64][WSTR]
    __nv_bfloat16* wu = (__nv_bfloat16*)(smem_raw + SMEM_WU_OFF);  // [2][128][SPAD] (union)
    __nv_bfloat16* gs = (__nv_bfloat16*)(smem_raw + SMEM_GS_OFF);  // [64][SPAD]
    float*         cf = (float*)(smem_raw + SMEM_CF_OFF);          // [128]
    float*         smu = (float*)(smem_raw + SMEM_MU_OFF);         // [64]
    float*         srs = (float*)(smem_raw + SMEM_RS_OFF);         // [64]

    const int tid  = threadIdx.x;
    const int warp = tid >> 5, lane = tid & 31;
    const int g    = lane >> 2, t4 = lane & 3;     // mma quad decomposition
    const int wm   = warp >> 2, wn = warp & 3;     // 4x4 warp grid
    const int row0 = blockIdx.x * MTILE;

    if (tid < 128) cf[tid] = g_cf[tid];

    // x loader mapping: row lr (0..63), col-group colg (0..7), 16 contiguous floats
    const int lr = tid >> 3, colg = tid & 7;
    const float* xrow = x + (size_t)(row0 + lr) * DIM + colg * 16;

    // wd cp.async mapping: 64 rows x (8 thr/row x 16 bf16)
    const int wdj = tid >> 3, wdc = (tid & 7) * 16;
    // wu cp.async mapping: 128 rows x (4 thr/row x 16 bf16)
    const int wun = tid >> 2, wuc = (tid & 3) * 16;

    // ldmatrix lane address components
    const int aRow   = wm * 16 + (lane & 15);                      // A frags (xs / gs)
    const int aKoff  = (lane >> 4) << 3;
    const int bRow   = wn * 16 + ((lane >> 4) << 3) + (lane & 7);  // B frags (wd)
    const int bKoff  = ((lane >> 3) & 1) << 3;
    const int bBrow0 = wn * 32 + ((lane >> 4) << 3) + (lane & 7);  // phase-B B (wu)
    const int bBrow1 = bBrow0 + 16;

    // ---- phase A prologue ----
    cp16(wd + (size_t)wdj * WSTR + wdc,     g_WdT + (size_t)wdj * DIM + wdc);
    cp16(wd + (size_t)wdj * WSTR + wdc + 8, g_WdT + (size_t)wdj * DIM + wdc + 8);
    cp_commit();

    float4 q0 = *(const float4*)(xrow);
    float4 q1 = *(const float4*)(xrow + 4);
    float4 q2 = *(const float4*)(xrow + 8);
    float4 q3 = *(const float4*)(xrow + 12);

    float s1 = 0.f, s2 = 0.f;
    float acc1[2][4] = {};

    // ---- phase A: stage x (bf16) + stats + GEMM1, K-chunk=128, double-buffered ----
#pragma unroll 1
    for (int it = 0; it < NKC; it++) {
        const int cur = it & 1;
        // stats
        s1 += q0.x + q0.y + q0.z + q0.w + q1.x + q1.y + q1.z + q1.w
            + q2.x + q2.y + q2.z + q2.w + q3.x + q3.y + q3.z + q3.w;
        s2 += q0.x*q0.x + q0.y*q0.y + q0.z*q0.z + q0.w*q0.w
            + q1.x*q1.x + q1.y*q1.y + q1.z*q1.z + q1.w*q1.w
            + q2.x*q2.x + q2.y*q2.y + q2.z*q2.z + q2.w*q2.w
            + q3.x*q3.x + q3.y*q3.y + q3.z*q3.z + q3.w*q3.w;
        // pack + store 16 bf16
        uint4 lo = make_uint4(pack_bf2(q0.x, q0.y), pack_bf2(q0.z, q0.w),
                              pack_bf2(q1.x, q1.y), pack_bf2(q1.z, q1.w));
        uint4 hi = make_uint4(pack_bf2(q2.x, q2.y), pack_bf2(q2.z, q2.w),
                              pack_bf2(q3.x, q3.y), pack_bf2(q3.z, q3.w));
        *(uint4*)(xs + (size_t)(cur * 64 + lr) * WSTR + colg * 16)     = lo;
        *(uint4*)(xs + (size_t)(cur * 64 + lr) * WSTR + colg * 16 + 8) = hi;
        // prefetch next x chunk (lands during mma)
        if (it + 1 < NKC) {
            const float* qp = xrow + (it + 1) * KC;
            q0 = *(const float4*)(qp);
            q1 = *(const float4*)(qp + 4);
            q2 = *(const float4*)(qp + 8);
            q3 = *(const float4*)(qp + 12);
        }
        cp_wait0();          // wd[cur] arrived
        __syncthreads();     // xs[cur]+wd[cur] visible; other buffers' readers drained
        if (it + 1 < NKC) {  // prefetch next wd chunk into other buffer
            __nv_bfloat16* dst = wd + (size_t)((1 - cur) * 64 + wdj) * WSTR + wdc;
            const __nv_bfloat16* src = g_WdT + (size_t)wdj * DIM + (it + 1) * KC + wdc;
            cp16(dst, src);
            cp16(dst + 8, src + 8);
            cp_commit();
        }
#pragma unroll
        for (int ks = 0; ks < 8; ks++) {
            uint32_t a[4];
            ldsm_x4(a[0], a[1], a[2], a[3],
                    xs + (size_t)(cur * 64 + aRow) * WSTR + ks * 16 + aKoff);
            uint32_t b0, b1, b2, b3;
            ldsm_x4(b0, b1, b2, b3,
                    wd + (size_t)(cur * 64 + bRow) * WSTR + ks * 16 + bKoff);
            uint32_t p0[2] = {b0, b1}, p1[2] = {b2, b3};
            mma_bf16(acc1[0], a, p0);
            mma_bf16(acc1[1], a, p1);
        }
    }

    // ---- LN stats: reduce over the 8 lanes covering each row ----
#pragma unroll
    for (int off = 1; off <= 4; off <<= 1) {
        s1 += __shfl_xor_sync(0xffffffffu, s1, off);
        s2 += __shfl_xor_sync(0xffffffffu, s2, off);
    }
    if (colg == 0) {
        float m = s1 * (1.0f / 1024.0f);
        smu[lr] = m;
        srs[lr] = rsqrtf(s2 * (1.0f / 1024.0f) - m * m + 1e-5f);
    }
    __syncthreads();   // stats published; all xs/wd reads done -> union free

    // prefetch wu chunk 0
    cp16(wu + (size_t)wun * SPAD + wuc,     g_WuT + (size_t)wun * BOT + wuc);
    cp16(wu + (size_t)wun * SPAD + wuc + 8, g_WuT + (size_t)wun * BOT + wuc + 8);
    cp_commit();

    // ---- affine correction + exact GELU -> gs ----
    {
        const float mua = smu[wm * 16 + g],     rsa = srs[wm * 16 + g];
        const float mub = smu[wm * 16 + g + 8], rsb = srs[wm * 16 + g + 8];
#pragma unroll
        for (int h = 0; h < 2; h++) {
            int j0 = wn * 16 + h * 8 + t4 * 2;
            float c0 = cf[j0], c1 = cf[j0 + 1];
            float f0 = cf[64 + j0], f1 = cf[64 + j0 + 1];
            float z00 = rsa * (acc1[h][0] - mua * c0) + f0;
            float z01 = rsa * (acc1[h][1] - mua * c1) + f1;
            float z10 = rsb * (acc1[h][2] - mub * c0) + f0;
            float z11 = rsb * (acc1[h][3] - mub * c1) + f1;
            z00 = 0.5f * z00 * (1.0f + erff(z00 * 0.70710678118f));
            z01 = 0.5f * z01 * (1.0f + erff(z01 * 0.70710678118f));
            z10 = 0.5f * z10 * (1.0f + erff(z10 * 0.70710678118f));
            z11 = 0.5f * z11 * (1.0f + erff(z11 * 0.70710678118f));
            *(uint32_t*)&gs[(wm * 16 + g) * SPAD + j0]     = pack_bf2(z00, z01);
            *(uint32_t*)&gs[(wm * 16 + g + 8) * SPAD + j0] = pack_bf2(z10, z11);
        }
    }
    const float scale = *scale_p;

    // ---- phase B: GEMM2 (gelu @ w_up), N-chunked, fused residual epilogue ----
#pragma unroll 1
    for (int nc = 0; nc < NNC; nc++) {
        const int cur = nc & 1;
        cp_wait0();
        __syncthreads();   // wu[cur] + gs visible; wu[1-cur] readers done
        if (nc + 1 < NNC) {
            __nv_bfloat16* dst = wu + (size_t)((1 - cur) * 128 + wun) * SPAD + wuc;
            const __nv_bfloat16* src = g_WuT + (size_t)((nc + 1) * NCH + wun) * BOT + wuc;
            cp16(dst, src);
            cp16(dst + 8, src + 8);
            cp_commit();
        }
        float acc2[4][4] = {};
#pragma unroll
        for (int ks = 0; ks < 4; ks++) {
            uint32_t a[4];
            ldsm_x4(a[0], a[1], a[2], a[3],
                    gs + (size_t)aRow * SPAD + ks * 16 + aKoff);
            uint32_t b0, b1, b2, b3;
            ldsm_x4(b0, b1, b2, b3,
                    wu + (size_t)(cur * 128 + bBrow0) * SPAD + ks * 16 + bKoff);
            uint32_t p0[2] = {b0, b1}, p1[2] = {b2, b3};
            mma_bf16(acc2[0], a, p0);
            mma_bf16(acc2[1], a, p1);
            ldsm_x4(b0, b1, b2, b3,
                    wu + (size_t)(cur * 128 + bBrow1) * SPAD + ks * 16 + bKoff);
            uint32_t p2[2] = {b0, b1}, p3[2] = {b2, b3};
            mma_bf16(acc2[2], a, p2);
            mma_bf16(acc2[3], a, p3);
        }
        // epilogue: out = x + scale*(h + b_up)
        const int rowa = row0 + wm * 16 + g;
#pragma unroll
        for (int sub = 0; sub < 4; sub++) {
            int col = nc * NCH + wn * 32 + sub * 8 + t4 * 2;
            float2 bu = *(const float2*)(b_up + col);
            float2 xa = *(const float2*)(x + (size_t)rowa * DIM + col);
            float2 xb = *(const float2*)(x + (size_t)(rowa + 8) * DIM + col);
            float2 oa, ob;
            oa.x = xa.x + scale * (acc2[sub][0] + bu.x);
            oa.y = xa.y + scale * (acc2[sub][1] + bu.y);
            ob.x = xb.x + scale * (acc2[sub][2] + bu.x);
            ob.y = xb.y + scale * (acc2[sub][3] + bu.y);
            *(float2*)(out + (size_t)rowa * DIM + col)       = oa;
            *(float2*)(out + (size_t)(rowa + 8) * DIM + col) = ob;
        }
    }
}

// ---------------- launch ----------------
extern "C" void kernel_launch(void* const* d_in, const int* in_sizes, int n_in,
                              void* d_out, int out_size)
{
    const float* x      = (const float*)d_in[0];
    const float* norm_w = (const float*)d_in[1];
    const float* norm_b = (const float*)d_in[2];
    const float* w_down = (const float*)d_in[3];
    const float* b_down = (const float*)d_in[4];
    const float* w_up   = (const float*)d_in[5];
    const float* b_up   = (const float*)d_in[6];
    const float* scale  = (const float*)d_in[7];
    float* out = (float*)d_out;

    cudaFuncSetAttribute(adapter_kernel,
                         cudaFuncAttributeMaxDynamicSharedMemorySize, SMEM_TOTAL);

    prep_kernel<<<17, 256>>>(norm_w, norm_b, w_down, b_down, w_up);
    adapter_kernel<<<TOT_ROWS / MTILE, NTHR, SMEM_TOTAL>>>(x, b_up, scale, out);
}